// round 15
// baseline (speedup 1.0000x reference)
#include <cuda_runtime.h>
#include <cuda_fp16.h>
#include <cstdint>

#define PI_F 3.14159265358979323846f
#define CUTOFF_F 5.0f
#define MAX_N 50000

// linear fp16 scalar_out (gemm output) + packed layouts for the edge kernel
__device__ __half g_so16[(size_t)MAX_N * 192];  // [node][f] linear
__device__ __half2 g_sos[(size_t)MAX_N * 32];   // (so[128+2l], so[129+2l])
__device__ uint2  g_pnv[(size_t)MAX_N * 64];    // half4 (nv0*so_c, nv1*so_c, nv2*so_c, so[64+c])
__device__ int g_edge_is64;

__device__ __forceinline__ unsigned h2_as_u32(__half2 h) {
    return *reinterpret_cast<unsigned*>(&h);
}
__device__ __forceinline__ __half2 u32_as_h2(unsigned u) {
    return *reinterpret_cast<__half2*>(&u);
}

// packed f32x2 fma
__device__ __forceinline__ unsigned long long fma2(unsigned long long a,
                                                   unsigned long long b,
                                                   unsigned long long c) {
    unsigned long long d;
    asm("fma.rn.f32x2 %0, %1, %2, %3;" : "=l"(d) : "l"(a), "l"(b), "l"(c));
    return d;
}

__device__ __forceinline__ unsigned long long pack2(float w) {
    unsigned long long r;
    asm("mov.b64 %0, {%1, %1};" : "=l"(r) : "f"(w));
    return r;
}

__device__ __forceinline__ void red_v2(float* p, float a, float b) {
    asm volatile("red.global.add.v2.f32 [%0], {%1, %2};"
                 :: "l"(p), "f"(a), "f"(b) : "memory");
}

// ---------------------------------------------------------------------------
// Kernel 0: detect whether edge array is int64 (odd int32 words all zero)
// ---------------------------------------------------------------------------
__global__ void detect_kernel(const int* __restrict__ edge32, int n_check)
{
    __shared__ int any_nonzero;
    if (threadIdx.x == 0) any_nonzero = 0;
    __syncthreads();
    for (int i = threadIdx.x; i < n_check; i += blockDim.x)
        if (edge32[2 * i + 1] != 0) any_nonzero = 1;
    __syncthreads();
    if (threadIdx.x == 0) g_edge_is64 = (any_nonzero == 0) ? 1 : 0;
}

// ---------------------------------------------------------------------------
// Kernel 1: node GEMM. 32 nodes/block, 128 threads. Writes g_so16 (fp16).
// ---------------------------------------------------------------------------
__global__ void __launch_bounds__(128) gemm_kernel(
    const float* __restrict__ ns, const float* __restrict__ W1,
    const float* __restrict__ b1, const float* __restrict__ W2,
    const float* __restrict__ b2, float* __restrict__ out_s, int N)
{
    __shared__ __align__(16) float W1s[64 * 64];
    __shared__ __align__(16) float xs[32 * 64];
    __shared__ __align__(16) float hs[32 * 64];
    __shared__ float b1s[64];
    __shared__ float b2s[192];

    int tid = threadIdx.x;
    for (int i = tid; i < 4096; i += 128) W1s[i] = W1[i];
    if (tid < 64) b1s[tid] = b1[tid];
    if (tid < 64) {
        b2s[tid] = b2[tid];
        b2s[tid + 64] = b2[tid + 64];
        b2s[tid + 128] = b2[tid + 128];
    }
    int base = blockIdx.x * 32;
    for (int i = tid; i < 32 * 64; i += 128) {
        int node = base + (i >> 6);
        float v = (node < N) ? ns[(size_t)base * 64 + i] : 0.f;
        xs[i] = v;
        if (node < N) out_s[(size_t)base * 64 + i] = v;  // residual init
    }
    __syncthreads();

    int fg = tid & 15;
    int ng = tid >> 4;
    int fb = fg * 4, n0 = ng * 4;

    float acc[4][4];
#pragma unroll
    for (int g = 0; g < 4; g++)
#pragma unroll
        for (int k = 0; k < 4; k++) acc[g][k] = 0.f;
#pragma unroll 8
    for (int i = 0; i < 64; i++) {
        float4 w = reinterpret_cast<const float4*>(W1s)[i * 16 + fg];
#pragma unroll
        for (int g = 0; g < 4; g++) {
            float x = xs[(n0 + g) * 64 + i];
            acc[g][0] = fmaf(x, w.x, acc[g][0]);
            acc[g][1] = fmaf(x, w.y, acc[g][1]);
            acc[g][2] = fmaf(x, w.z, acc[g][2]);
            acc[g][3] = fmaf(x, w.w, acc[g][3]);
        }
    }
#pragma unroll
    for (int g = 0; g < 4; g++) {
        float4 hv;
        float* hp = (float*)&hv;
#pragma unroll
        for (int k = 0; k < 4; k++) {
            float v = acc[g][k] + b1s[fb + k];
            hp[k] = v / (1.f + __expf(-v));
        }
        reinterpret_cast<float4*>(&hs[(n0 + g) * 64 + fb])[0] = hv;
    }
    __syncthreads();

#pragma unroll 1
    for (int p = 0; p < 3; p++) {
#pragma unroll
        for (int g = 0; g < 4; g++)
#pragma unroll
            for (int k = 0; k < 4; k++) acc[g][k] = 0.f;
#pragma unroll 8
        for (int i = 0; i < 64; i++) {
            float4 w = __ldg(reinterpret_cast<const float4*>(W2) + i * 48 + p * 16 + fg);
#pragma unroll
            for (int g = 0; g < 4; g++) {
                float h = hs[(n0 + g) * 64 + i];
                acc[g][0] = fmaf(h, w.x, acc[g][0]);
                acc[g][1] = fmaf(h, w.y, acc[g][1]);
                acc[g][2] = fmaf(h, w.z, acc[g][2]);
                acc[g][3] = fmaf(h, w.w, acc[g][3]);
            }
        }
#pragma unroll
        for (int g = 0; g < 4; g++) {
            int node = base + n0 + g;
            if (node < N) {
                size_t idx = (size_t)node * 192 + p * 64 + fb;
                __half2 h01 = __floats2half2_rn(acc[g][0] + b2s[p * 64 + fb + 0],
                                                acc[g][1] + b2s[p * 64 + fb + 1]);
                __half2 h23 = __floats2half2_rn(acc[g][2] + b2s[p * 64 + fb + 2],
                                                acc[g][3] + b2s[p * 64 + fb + 3]);
                reinterpret_cast<__half2*>(&g_so16[idx])[0] = h01;
                reinterpret_cast<__half2*>(&g_so16[idx])[1] = h23;
            }
        }
    }
}

// ---------------------------------------------------------------------------
// Kernel 2: init packed layouts + vector residual. Thread per (node,c).
//  - out_v = node_vector (fp32 residual init)
//  - g_pnv = (nv0*so_c, nv1*so_c, nv2*so_c, so[64+c]) fp16
//  - c<32: g_sos = (so[128+2c], so[129+2c])
// ---------------------------------------------------------------------------
__global__ void init_pack_kernel(const float* __restrict__ nvec,
                                 float* __restrict__ out_v, int total)
{
    int i = blockIdx.x * blockDim.x + threadIdx.x;
    if (i >= total) return;
    int node = i >> 6, c = i & 63;
    size_t nb = (size_t)node * 192;
    float v0 = nvec[nb + c];
    float v1 = nvec[nb + 64 + c];
    float v2 = nvec[nb + 128 + c];
    out_v[nb + c]       = v0;
    out_v[nb + 64 + c]  = v1;
    out_v[nb + 128 + c] = v2;
    float so_c  = __half2float(g_so16[nb + c]);
    float so64  = __half2float(g_so16[nb + 64 + c]);
    __half2 a = __floats2half2_rn(v0 * so_c, v1 * so_c);
    __half2 b = __floats2half2_rn(v2 * so_c, so64);
    g_pnv[i] = make_uint2(h2_as_u32(a), h2_as_u32(b));
    if (c < 32)
        g_sos[(size_t)node * 32 + c] =
            __halves2half2(g_so16[nb + 128 + 2 * c], g_so16[nb + 129 + 2 * c]);
}

// ---------------------------------------------------------------------------
// Kernel 3: edge kernel. 192 threads, 64 edges per tile, 5 blocks/SM.
// vec warps: 1 LDG.64 gather + 3 RED.32 per edge-thread, direct into out_v.
// ---------------------------------------------------------------------------
__global__ void __launch_bounds__(192, 5) edge_kernel(
    const void* __restrict__ edge_raw, const float* __restrict__ ediff,
    const float* __restrict__ edist, const float* __restrict__ Wf,
    const float* __restrict__ bf,
    float* __restrict__ out_s, float* __restrict__ out_v,
    int E, int ntiles)
{
    __shared__ __align__(16) float rbf_s[20 * 64];  // [n][e]
    __shared__ __align__(16) float4 meta_s[64];     // (u0,u1,u2,cut)
    __shared__ __align__(8)  int2 sd_s[64];         // (src,dst)

    int tid  = threadIdx.x;
    int wid  = tid >> 5;
    int lane = tid & 31;
    int is64 = g_edge_is64;
    const int* e32 = (const int*)edge_raw;
    const long long* e64 = (const long long*)edge_raw;

    bool is_vec = (wid < 4);
    int eoff = is_vec ? ((wid & 2) ? 32 : 0) : ((wid == 5) ? 32 : 0);
    int cA, cB;
    if (is_vec) {
        int cc = ((wid & 1) << 5) + lane;  // 0..63
        cA = cc; cB = 64 + cc;
    } else {
        cA = 128 + 2 * lane; cB = cA + 1;  // adjacent pair
    }

    float wfA[20], wfB[20];
#pragma unroll
    for (int n = 0; n < 20; n++) {
        wfA[n] = __ldg(&Wf[n * 192 + cA]);
        wfB[n] = __ldg(&Wf[n * 192 + cB]);
    }
    float bfA = __ldg(&bf[cA]);
    float bfB = __ldg(&bf[cB]);
    int c = cA & 63;  // channel within 64-block (valid for vec warps)

    for (int t = blockIdx.x; t < ntiles; t += gridDim.x) {
        int ebase = t * 64;
        __syncthreads();  // protect smem from previous tile's readers

        // meta (warps 0-1) + rbf (all threads)
        if (tid < 64) {
            int e = ebase + tid;
            if (e < E) {
                float d = __ldg(&edist[e]);
                float inv = __fdividef(1.f, d);
                float cut = (d < CUTOFF_F) ? 0.5f * (__cosf((PI_F / CUTOFF_F) * d) + 1.f) : 0.f;
                int sv, dv;
                if (is64) {
                    dv = (int)e64[2 * (size_t)e + 0];
                    sv = (int)e64[2 * (size_t)e + 1];
                } else {
                    dv = e32[2 * (size_t)e + 0];
                    sv = e32[2 * (size_t)e + 1];
                }
                sd_s[tid] = make_int2(sv, dv);
                meta_s[tid] = make_float4(__ldg(&ediff[3 * (size_t)e + 0]) * inv,
                                          __ldg(&ediff[3 * (size_t)e + 1]) * inv,
                                          __ldg(&ediff[3 * (size_t)e + 2]) * inv,
                                          cut);
            } else {
                sd_s[tid] = make_int2(0, 0);
                meta_s[tid] = make_float4(0.f, 0.f, 0.f, 0.f);
            }
        }
        for (int idx = tid; idx < 1280; idx += 192) {
            int n = idx >> 6, e = idx & 63;
            int ge = ebase + e;
            float d = (ge < E) ? __ldg(&edist[ge]) : 1.f;
            rbf_s[idx] = __fdividef(__sinf(d * ((float)(n + 1) * (PI_F / CUTOFF_F))), d);
        }
        __syncthreads();

        // 8 groups of 4 edges within this warp's 32-edge slice
#pragma unroll 1
        for (int g = 0; g < 8; g++) {
            unsigned long long a01 = 0ull, a23 = 0ull;
            unsigned long long b01 = 0ull, b23 = 0ull;
#pragma unroll
            for (int n = 0; n < 20; n++) {
                ulonglong2 rr = *reinterpret_cast<const ulonglong2*>(
                    &rbf_s[n * 64 + eoff + g * 4]);
                unsigned long long wA = pack2(wfA[n]);
                unsigned long long wB = pack2(wfB[n]);
                a01 = fma2(rr.x, wA, a01);
                a23 = fma2(rr.y, wA, a23);
                b01 = fma2(rr.x, wB, b01);
                b23 = fma2(rr.y, wB, b23);
            }
            float fa[4], fb[4];
            fa[0] = __uint_as_float((unsigned)a01);
            fa[1] = __uint_as_float((unsigned)(a01 >> 32));
            fa[2] = __uint_as_float((unsigned)a23);
            fa[3] = __uint_as_float((unsigned)(a23 >> 32));
            fb[0] = __uint_as_float((unsigned)b01);
            fb[1] = __uint_as_float((unsigned)(b01 >> 32));
            fb[2] = __uint_as_float((unsigned)b23);
            fb[3] = __uint_as_float((unsigned)(b23 >> 32));

            if (is_vec) {
#pragma unroll
                for (int j = 0; j < 4; j++) {
                    int e = eoff + g * 4 + j;
                    int2 sd = sd_s[e];
                    float4 mu = meta_s[e];
                    uint2 p = __ldg(&g_pnv[(unsigned)sd.x * 64u + c]);
                    float2 p01 = __half22float2(u32_as_h2(p.x));
                    float2 p2s = __half22float2(u32_as_h2(p.y));
                    float A = (fa[j] + bfA) * mu.w;            // gs factor (so folded into pnv)
                    float B = (fb[j] + bfB) * mu.w * p2s.y;    // ge
                    unsigned ob = (unsigned)sd.y * 192u + c;
                    atomicAdd(&out_v[ob],       fmaf(p01.x, A, B * mu.x));
                    atomicAdd(&out_v[ob + 64],  fmaf(p01.y, A, B * mu.y));
                    atomicAdd(&out_v[ob + 128], fmaf(p2s.x, A, B * mu.z));
                }
            } else {
#pragma unroll
                for (int j = 0; j < 4; j++) {
                    int e = eoff + g * 4 + j;
                    int2 sd = sd_s[e];
                    float cut = meta_s[e].w;
                    __half2 ss = __ldg(&g_sos[(unsigned)sd.x * 32u + lane]);
                    float2 ssf = __half22float2(ss);
                    float msA = (fa[j] + bfA) * cut * ssf.x;
                    float msB = (fb[j] + bfB) * cut * ssf.y;
                    red_v2(&out_s[(unsigned)sd.y * 64u + 2 * lane], msA, msB);
                }
            }
        }
    }
}

// ---------------------------------------------------------------------------
extern "C" void kernel_launch(void* const* d_in, const int* in_sizes, int n_in,
                              void* d_out, int out_size)
{
    const float* ns     = (const float*)d_in[0];
    const float* nvec   = (const float*)d_in[1];
    const void*  ed     = (const void*)d_in[2];
    const float* ediff  = (const float*)d_in[3];
    const float* edist  = (const float*)d_in[4];
    const float* W1     = (const float*)d_in[5];
    const float* b1     = (const float*)d_in[6];
    const float* W2     = (const float*)d_in[7];
    const float* b2     = (const float*)d_in[8];
    const float* Wf     = (const float*)d_in[9];
    const float* bf     = (const float*)d_in[10];

    int N = in_sizes[0] / 64;
    int E = in_sizes[4];  // edge_dist has E elements

    float* out_s = (float*)d_out;
    float* out_v = out_s + (size_t)N * 64;

    // 0) detect edge index dtype (int32 vs int64)
    int n_check = (E < 1024) ? E : 1024;
    detect_kernel<<<1, 256>>>((const int*)ed, n_check);

    // 1) node MLP (+ scalar residual init, linear fp16 scalar_out)
    gemm_kernel<<<(N + 31) / 32, 128>>>(ns, W1, b1, W2, b2, out_s, N);

    // 2) init packed layouts + vector residual
    int total = N * 64;
    init_pack_kernel<<<(total + 255) / 256, 256>>>(nvec, out_v, total);

    // 3) edge messages + scatter (direct into out_s / out_v)
    int ntiles = (E + 63) / 64;
    int grid = ntiles < 740 ? ntiles : 740;
    edge_kernel<<<grid, 192>>>(ed, ediff, edist, Wf, bf,
                               out_s, out_v, E, ntiles);
}

// round 16
// speedup vs baseline: 1.0306x; 1.0306x over previous
#include <cuda_runtime.h>
#include <cuda_fp16.h>
#include <cstdint>

#define PI_F 3.14159265358979323846f
#define CUTOFF_F 5.0f
#define MAX_N 50000

// linear fp16 scalar_out (gemm output) + packed layouts for the edge kernel
__device__ __half g_so16[(size_t)MAX_N * 192];  // [node][f] linear
__device__ __half2 g_sos[(size_t)MAX_N * 32];   // (so[128+2l], so[129+2l])
__device__ uint2  g_pnv[(size_t)MAX_N * 64];    // half4 (nv0*so_c, nv1*so_c, nv2*so_c, so[64+c])
__device__ float4 g_accv[(size_t)MAX_N * 64];   // fp32 accum (a0,a1,a2,pad)
__device__ int g_edge_is64;

__device__ __forceinline__ unsigned h2_as_u32(__half2 h) {
    return *reinterpret_cast<unsigned*>(&h);
}
__device__ __forceinline__ __half2 u32_as_h2(unsigned u) {
    return *reinterpret_cast<__half2*>(&u);
}

// packed f32x2 fma
__device__ __forceinline__ unsigned long long fma2(unsigned long long a,
                                                   unsigned long long b,
                                                   unsigned long long c) {
    unsigned long long d;
    asm("fma.rn.f32x2 %0, %1, %2, %3;" : "=l"(d) : "l"(a), "l"(b), "l"(c));
    return d;
}

__device__ __forceinline__ unsigned long long pack2(float w) {
    unsigned long long r;
    asm("mov.b64 %0, {%1, %1};" : "=l"(r) : "f"(w));
    return r;
}

__device__ __forceinline__ void red_v4(float* p, float a, float b, float c, float d) {
    asm volatile("red.global.add.v4.f32 [%0], {%1, %2, %3, %4};"
                 :: "l"(p), "f"(a), "f"(b), "f"(c), "f"(d) : "memory");
}
__device__ __forceinline__ void red_v2(float* p, float a, float b) {
    asm volatile("red.global.add.v2.f32 [%0], {%1, %2};"
                 :: "l"(p), "f"(a), "f"(b) : "memory");
}

// ---------------------------------------------------------------------------
// Kernel 0: detect whether edge array is int64 (odd int32 words all zero)
// ---------------------------------------------------------------------------
__global__ void detect_kernel(const int* __restrict__ edge32, int n_check)
{
    __shared__ int any_nonzero;
    if (threadIdx.x == 0) any_nonzero = 0;
    __syncthreads();
    for (int i = threadIdx.x; i < n_check; i += blockDim.x)
        if (edge32[2 * i + 1] != 0) any_nonzero = 1;
    __syncthreads();
    if (threadIdx.x == 0) g_edge_is64 = (any_nonzero == 0) ? 1 : 0;
}

// ---------------------------------------------------------------------------
// Kernel 1: node GEMM. 32 nodes/block, 128 threads. Writes g_so16 (fp16).
// ---------------------------------------------------------------------------
__global__ void __launch_bounds__(128) gemm_kernel(
    const float* __restrict__ ns, const float* __restrict__ W1,
    const float* __restrict__ b1, const float* __restrict__ W2,
    const float* __restrict__ b2, float* __restrict__ out_s, int N)
{
    __shared__ __align__(16) float W1s[64 * 64];
    __shared__ __align__(16) float xs[32 * 64];
    __shared__ __align__(16) float hs[32 * 64];
    __shared__ float b1s[64];
    __shared__ float b2s[192];

    int tid = threadIdx.x;
    for (int i = tid; i < 4096; i += 128) W1s[i] = W1[i];
    if (tid < 64) b1s[tid] = b1[tid];
    if (tid < 64) {
        b2s[tid] = b2[tid];
        b2s[tid + 64] = b2[tid + 64];
        b2s[tid + 128] = b2[tid + 128];
    }
    int base = blockIdx.x * 32;
    for (int i = tid; i < 32 * 64; i += 128) {
        int node = base + (i >> 6);
        float v = (node < N) ? ns[(size_t)base * 64 + i] : 0.f;
        xs[i] = v;
        if (node < N) out_s[(size_t)base * 64 + i] = v;  // residual init
    }
    __syncthreads();

    int fg = tid & 15;
    int ng = tid >> 4;
    int fb = fg * 4, n0 = ng * 4;

    float acc[4][4];
#pragma unroll
    for (int g = 0; g < 4; g++)
#pragma unroll
        for (int k = 0; k < 4; k++) acc[g][k] = 0.f;
#pragma unroll 8
    for (int i = 0; i < 64; i++) {
        float4 w = reinterpret_cast<const float4*>(W1s)[i * 16 + fg];
#pragma unroll
        for (int g = 0; g < 4; g++) {
            float x = xs[(n0 + g) * 64 + i];
            acc[g][0] = fmaf(x, w.x, acc[g][0]);
            acc[g][1] = fmaf(x, w.y, acc[g][1]);
            acc[g][2] = fmaf(x, w.z, acc[g][2]);
            acc[g][3] = fmaf(x, w.w, acc[g][3]);
        }
    }
#pragma unroll
    for (int g = 0; g < 4; g++) {
        float4 hv;
        float* hp = (float*)&hv;
#pragma unroll
        for (int k = 0; k < 4; k++) {
            float v = acc[g][k] + b1s[fb + k];
            hp[k] = v / (1.f + __expf(-v));
        }
        reinterpret_cast<float4*>(&hs[(n0 + g) * 64 + fb])[0] = hv;
    }
    __syncthreads();

#pragma unroll 1
    for (int p = 0; p < 3; p++) {
#pragma unroll
        for (int g = 0; g < 4; g++)
#pragma unroll
            for (int k = 0; k < 4; k++) acc[g][k] = 0.f;
#pragma unroll 8
        for (int i = 0; i < 64; i++) {
            float4 w = __ldg(reinterpret_cast<const float4*>(W2) + i * 48 + p * 16 + fg);
#pragma unroll
            for (int g = 0; g < 4; g++) {
                float h = hs[(n0 + g) * 64 + i];
                acc[g][0] = fmaf(h, w.x, acc[g][0]);
                acc[g][1] = fmaf(h, w.y, acc[g][1]);
                acc[g][2] = fmaf(h, w.z, acc[g][2]);
                acc[g][3] = fmaf(h, w.w, acc[g][3]);
            }
        }
#pragma unroll
        for (int g = 0; g < 4; g++) {
            int node = base + n0 + g;
            if (node < N) {
                size_t idx = (size_t)node * 192 + p * 64 + fb;
                __half2 h01 = __floats2half2_rn(acc[g][0] + b2s[p * 64 + fb + 0],
                                                acc[g][1] + b2s[p * 64 + fb + 1]);
                __half2 h23 = __floats2half2_rn(acc[g][2] + b2s[p * 64 + fb + 2],
                                                acc[g][3] + b2s[p * 64 + fb + 3]);
                reinterpret_cast<__half2*>(&g_so16[idx])[0] = h01;
                reinterpret_cast<__half2*>(&g_so16[idx])[1] = h23;
            }
        }
    }
}

// ---------------------------------------------------------------------------
// Kernel 2: init packed layouts. Thread per (node,c), c in 0..63.
//  - g_accv = (nv0,nv1,nv2,0) fp32  (vector accumulator incl. residual)
//  - g_pnv  = (nv0*so_c, nv1*so_c, nv2*so_c, so[64+c]) fp16
//  - c<32: g_sos = (so[128+2c], so[129+2c])
// ---------------------------------------------------------------------------
__global__ void init_pack_kernel(const float* __restrict__ nvec, int total)
{
    int i = blockIdx.x * blockDim.x + threadIdx.x;
    if (i >= total) return;
    int node = i >> 6, c = i & 63;
    size_t nb = (size_t)node * 192;
    float v0 = nvec[nb + c];
    float v1 = nvec[nb + 64 + c];
    float v2 = nvec[nb + 128 + c];
    g_accv[i] = make_float4(v0, v1, v2, 0.f);
    float so_c  = __half2float(g_so16[nb + c]);
    float so64  = __half2float(g_so16[nb + 64 + c]);
    __half2 a = __floats2half2_rn(v0 * so_c, v1 * so_c);
    __half2 b = __floats2half2_rn(v2 * so_c, so64);
    g_pnv[i] = make_uint2(h2_as_u32(a), h2_as_u32(b));
    if (c < 32)
        g_sos[(size_t)node * 32 + c] =
            __halves2half2(g_so16[nb + 128 + 2 * c], g_so16[nb + 129 + 2 * c]);
}

// ---------------------------------------------------------------------------
// Kernel 4: unpermute g_accv -> out_v
// ---------------------------------------------------------------------------
__global__ void unpack_kernel(float* __restrict__ out_v, int total)
{
    int i = blockIdx.x * blockDim.x + threadIdx.x;
    if (i >= total) return;
    int node = i >> 6, c = i & 63;
    float4 a = g_accv[i];
    size_t nb = (size_t)node * 192;
    out_v[nb + c]       = a.x;
    out_v[nb + 64 + c]  = a.y;
    out_v[nb + 128 + c] = a.z;
}

// ---------------------------------------------------------------------------
// Kernel 3: edge kernel. 192 threads, 64 edges per tile, 5 blocks/SM.
// rbf via Chebyshev recurrence: 3 MUFU/edge instead of ~42.
// ---------------------------------------------------------------------------
__global__ void __launch_bounds__(192, 5) edge_kernel(
    const void* __restrict__ edge_raw, const float* __restrict__ ediff,
    const float* __restrict__ edist, const float* __restrict__ Wf,
    const float* __restrict__ bf,
    float* __restrict__ out_s,
    int E, int ntiles)
{
    __shared__ __align__(16) float rbf_s[20 * 64];  // [n][e]
    __shared__ __align__(16) float4 meta_s[64];     // (u0,u1,u2,cut)
    __shared__ __align__(8)  int2 sd_s[64];         // (src,dst)

    int tid  = threadIdx.x;
    int wid  = tid >> 5;
    int lane = tid & 31;
    int is64 = g_edge_is64;
    const int* e32 = (const int*)edge_raw;
    const long long* e64 = (const long long*)edge_raw;

    bool is_vec = (wid < 4);
    int eoff = is_vec ? ((wid & 2) ? 32 : 0) : ((wid == 5) ? 32 : 0);
    int cA, cB;
    if (is_vec) {
        int cc = ((wid & 1) << 5) + lane;  // 0..63
        cA = cc; cB = 64 + cc;
    } else {
        cA = 128 + 2 * lane; cB = cA + 1;  // adjacent pair
    }

    float wfA[20], wfB[20];
#pragma unroll
    for (int n = 0; n < 20; n++) {
        wfA[n] = __ldg(&Wf[n * 192 + cA]);
        wfB[n] = __ldg(&Wf[n * 192 + cB]);
    }
    float bfA = __ldg(&bf[cA]);
    float bfB = __ldg(&bf[cB]);
    int c = cA & 63;  // channel within 64-block (valid for vec warps)

    for (int t = blockIdx.x; t < ntiles; t += gridDim.x) {
        int ebase = t * 64;
        __syncthreads();  // protect smem from previous tile's readers

        // meta + rbf via sin recurrence (one thread per edge, warps 0-1)
        if (tid < 64) {
            int e = ebase + tid;
            float d = 1.f, u0 = 0.f, u1 = 0.f, u2 = 0.f;
            int sv = 0, dv = 0;
            bool valid = (e < E);
            if (valid) {
                d = __ldg(&edist[e]);
                if (is64) {
                    dv = (int)e64[2 * (size_t)e + 0];
                    sv = (int)e64[2 * (size_t)e + 1];
                } else {
                    dv = e32[2 * (size_t)e + 0];
                    sv = e32[2 * (size_t)e + 1];
                }
                u0 = __ldg(&ediff[3 * (size_t)e + 0]);
                u1 = __ldg(&ediff[3 * (size_t)e + 1]);
                u2 = __ldg(&ediff[3 * (size_t)e + 2]);
            }
            float inv = valid ? __frcp_rn(d) : 0.f;
            float x = d * (PI_F / CUTOFF_F);
            float sx, cx;
            __sincosf(x, &sx, &cx);
            float cut = (valid && d < CUTOFF_F) ? 0.5f * (cx + 1.f) : 0.f;
            sd_s[tid] = make_int2(sv, dv);
            meta_s[tid] = make_float4(u0 * inv, u1 * inv, u2 * inv, cut);
            // rbf[n] = sin((n+1)x)/d via s_{k+1} = 2cx*s_k - s_{k-1}
            float two_c = 2.f * cx;
            float s_prev = 0.f, s_cur = sx;
            if (!valid) { s_cur = 0.f; two_c = 0.f; }
#pragma unroll
            for (int n = 0; n < 20; n++) {
                rbf_s[n * 64 + tid] = s_cur * inv;
                float s_next = fmaf(two_c, s_cur, -s_prev);
                s_prev = s_cur;
                s_cur = s_next;
            }
        }
        __syncthreads();

        // 8 groups of 4 edges within this warp's 32-edge slice
#pragma unroll 1
        for (int g = 0; g < 8; g++) {
            unsigned long long a01 = 0ull, a23 = 0ull;
            unsigned long long b01 = 0ull, b23 = 0ull;
#pragma unroll
            for (int n = 0; n < 20; n++) {
                ulonglong2 rr = *reinterpret_cast<const ulonglong2*>(
                    &rbf_s[n * 64 + eoff + g * 4]);
                unsigned long long wA = pack2(wfA[n]);
                unsigned long long wB = pack2(wfB[n]);
                a01 = fma2(rr.x, wA, a01);
                a23 = fma2(rr.y, wA, a23);
                b01 = fma2(rr.x, wB, b01);
                b23 = fma2(rr.y, wB, b23);
            }
            float fa[4], fb[4];
            fa[0] = __uint_as_float((unsigned)a01);
            fa[1] = __uint_as_float((unsigned)(a01 >> 32));
            fa[2] = __uint_as_float((unsigned)a23);
            fa[3] = __uint_as_float((unsigned)(a23 >> 32));
            fb[0] = __uint_as_float((unsigned)b01);
            fb[1] = __uint_as_float((unsigned)(b01 >> 32));
            fb[2] = __uint_as_float((unsigned)b23);
            fb[3] = __uint_as_float((unsigned)(b23 >> 32));

            if (is_vec) {
#pragma unroll
                for (int j = 0; j < 4; j++) {
                    int e = eoff + g * 4 + j;
                    int2 sd = sd_s[e];
                    float4 mu = meta_s[e];
                    uint2 p = __ldg(&g_pnv[(unsigned)sd.x * 64u + c]);
                    float2 p01 = __half22float2(u32_as_h2(p.x));
                    float2 p2s = __half22float2(u32_as_h2(p.y));
                    float A = (fa[j] + bfA) * mu.w;            // gs factor (so folded into pnv)
                    float B = (fb[j] + bfB) * mu.w * p2s.y;    // ge
                    float m0 = fmaf(p01.x, A, B * mu.x);
                    float m1 = fmaf(p01.y, A, B * mu.y);
                    float m2 = fmaf(p2s.x, A, B * mu.z);
                    red_v4((float*)&g_accv[(unsigned)sd.y * 64u + c], m0, m1, m2, 0.f);
                }
            } else {
#pragma unroll
                for (int j = 0; j < 4; j++) {
                    int e = eoff + g * 4 + j;
                    int2 sd = sd_s[e];
                    float cut = meta_s[e].w;
                    __half2 ss = __ldg(&g_sos[(unsigned)sd.x * 32u + lane]);
                    float2 ssf = __half22float2(ss);
                    float msA = (fa[j] + bfA) * cut * ssf.x;
                    float msB = (fb[j] + bfB) * cut * ssf.y;
                    red_v2(&out_s[(unsigned)sd.y * 64u + 2 * lane], msA, msB);
                }
            }
        }
    }
}

// ---------------------------------------------------------------------------
extern "C" void kernel_launch(void* const* d_in, const int* in_sizes, int n_in,
                              void* d_out, int out_size)
{
    const float* ns     = (const float*)d_in[0];
    const float* nvec   = (const float*)d_in[1];
    const void*  ed     = (const void*)d_in[2];
    const float* ediff  = (const float*)d_in[3];
    const float* edist  = (const float*)d_in[4];
    const float* W1     = (const float*)d_in[5];
    const float* b1     = (const float*)d_in[6];
    const float* W2     = (const float*)d_in[7];
    const float* b2     = (const float*)d_in[8];
    const float* Wf     = (const float*)d_in[9];
    const float* bf     = (const float*)d_in[10];

    int N = in_sizes[0] / 64;
    int E = in_sizes[4];  // edge_dist has E elements

    float* out_s = (float*)d_out;
    float* out_v = out_s + (size_t)N * 64;

    // 0) detect edge index dtype (int32 vs int64)
    int n_check = (E < 1024) ? E : 1024;
    detect_kernel<<<1, 256>>>((const int*)ed, n_check);

    // 1) node MLP (+ scalar residual init, linear fp16 scalar_out)
    gemm_kernel<<<(N + 31) / 32, 128>>>(ns, W1, b1, W2, b2, out_s, N);

    // 2) init packed layouts (accv residual, pnv, sos)
    int total = N * 64;
    init_pack_kernel<<<(total + 255) / 256, 256>>>(nvec, total);

    // 3) edge messages + scatter
    int ntiles = (E + 63) / 64;
    int grid = ntiles < 740 ? ntiles : 740;
    edge_kernel<<<grid, 192>>>(ed, ediff, edist, Wf, bf,
                               out_s, E, ntiles);

    // 4) unpermute vector accumulator into out_v
    unpack_kernel<<<(total + 255) / 256, 256>>>(out_v, total);
}

// round 17
// speedup vs baseline: 1.0453x; 1.0143x over previous
#include <cuda_runtime.h>
#include <cuda_fp16.h>
#include <cstdint>

#define PI_F 3.14159265358979323846f
#define CUTOFF_F 5.0f
#define MAX_N 50000

// linear fp16 scalar_out (gemm output) + packed layouts for the edge kernel
__device__ __half g_so16[(size_t)MAX_N * 192];  // [node][f] linear
__device__ __half2 g_sos[(size_t)MAX_N * 32];   // (so[128+2l], so[129+2l])
__device__ uint2  g_pnv[(size_t)MAX_N * 64];    // half4 (nv0*so_c, nv1*so_c, nv2*so_c, so[64+c])
__device__ float4 g_accv[(size_t)MAX_N * 64];   // fp32 accum (a0,a1,a2,pad)
__device__ int g_edge_is64;

__device__ __forceinline__ unsigned h2_as_u32(__half2 h) {
    return *reinterpret_cast<unsigned*>(&h);
}
__device__ __forceinline__ __half2 u32_as_h2(unsigned u) {
    return *reinterpret_cast<__half2*>(&u);
}

// packed f32x2 fma
__device__ __forceinline__ unsigned long long fma2(unsigned long long a,
                                                   unsigned long long b,
                                                   unsigned long long c) {
    unsigned long long d;
    asm("fma.rn.f32x2 %0, %1, %2, %3;" : "=l"(d) : "l"(a), "l"(b), "l"(c));
    return d;
}

__device__ __forceinline__ unsigned long long pack2(float w) {
    unsigned long long r;
    asm("mov.b64 %0, {%1, %1};" : "=l"(r) : "f"(w));
    return r;
}

__device__ __forceinline__ void red_v4(float* p, float a, float b, float c, float d) {
    asm volatile("red.global.add.v4.f32 [%0], {%1, %2, %3, %4};"
                 :: "l"(p), "f"(a), "f"(b), "f"(c), "f"(d) : "memory");
}
__device__ __forceinline__ void red_v2(float* p, float a, float b) {
    asm volatile("red.global.add.v2.f32 [%0], {%1, %2};"
                 :: "l"(p), "f"(a), "f"(b) : "memory");
}

// ---------------------------------------------------------------------------
// Kernel 0: detect whether edge array is int64 (odd int32 words all zero)
// ---------------------------------------------------------------------------
__global__ void detect_kernel(const int* __restrict__ edge32, int n_check)
{
    __shared__ int any_nonzero;
    if (threadIdx.x == 0) any_nonzero = 0;
    __syncthreads();
    for (int i = threadIdx.x; i < n_check; i += blockDim.x)
        if (edge32[2 * i + 1] != 0) any_nonzero = 1;
    __syncthreads();
    if (threadIdx.x == 0) g_edge_is64 = (any_nonzero == 0) ? 1 : 0;
}

// ---------------------------------------------------------------------------
// Kernel 1: node GEMM. 32 nodes/block, 128 threads. Writes g_so16 (fp16).
// ---------------------------------------------------------------------------
__global__ void __launch_bounds__(128) gemm_kernel(
    const float* __restrict__ ns, const float* __restrict__ W1,
    const float* __restrict__ b1, const float* __restrict__ W2,
    const float* __restrict__ b2, float* __restrict__ out_s, int N)
{
    __shared__ __align__(16) float W1s[64 * 64];
    __shared__ __align__(16) float xs[32 * 64];
    __shared__ __align__(16) float hs[32 * 64];
    __shared__ float b1s[64];
    __shared__ float b2s[192];

    int tid = threadIdx.x;
    for (int i = tid; i < 4096; i += 128) W1s[i] = W1[i];
    if (tid < 64) b1s[tid] = b1[tid];
    if (tid < 64) {
        b2s[tid] = b2[tid];
        b2s[tid + 64] = b2[tid + 64];
        b2s[tid + 128] = b2[tid + 128];
    }
    int base = blockIdx.x * 32;
    for (int i = tid; i < 32 * 64; i += 128) {
        int node = base + (i >> 6);
        float v = (node < N) ? ns[(size_t)base * 64 + i] : 0.f;
        xs[i] = v;
        if (node < N) out_s[(size_t)base * 64 + i] = v;  // residual init
    }
    __syncthreads();

    int fg = tid & 15;
    int ng = tid >> 4;
    int fb = fg * 4, n0 = ng * 4;

    float acc[4][4];
#pragma unroll
    for (int g = 0; g < 4; g++)
#pragma unroll
        for (int k = 0; k < 4; k++) acc[g][k] = 0.f;
#pragma unroll 8
    for (int i = 0; i < 64; i++) {
        float4 w = reinterpret_cast<const float4*>(W1s)[i * 16 + fg];
#pragma unroll
        for (int g = 0; g < 4; g++) {
            float x = xs[(n0 + g) * 64 + i];
            acc[g][0] = fmaf(x, w.x, acc[g][0]);
            acc[g][1] = fmaf(x, w.y, acc[g][1]);
            acc[g][2] = fmaf(x, w.z, acc[g][2]);
            acc[g][3] = fmaf(x, w.w, acc[g][3]);
        }
    }
#pragma unroll
    for (int g = 0; g < 4; g++) {
        float4 hv;
        float* hp = (float*)&hv;
#pragma unroll
        for (int k = 0; k < 4; k++) {
            float v = acc[g][k] + b1s[fb + k];
            hp[k] = v / (1.f + __expf(-v));
        }
        reinterpret_cast<float4*>(&hs[(n0 + g) * 64 + fb])[0] = hv;
    }
    __syncthreads();

#pragma unroll 1
    for (int p = 0; p < 3; p++) {
#pragma unroll
        for (int g = 0; g < 4; g++)
#pragma unroll
            for (int k = 0; k < 4; k++) acc[g][k] = 0.f;
#pragma unroll 8
        for (int i = 0; i < 64; i++) {
            float4 w = __ldg(reinterpret_cast<const float4*>(W2) + i * 48 + p * 16 + fg);
#pragma unroll
            for (int g = 0; g < 4; g++) {
                float h = hs[(n0 + g) * 64 + i];
                acc[g][0] = fmaf(h, w.x, acc[g][0]);
                acc[g][1] = fmaf(h, w.y, acc[g][1]);
                acc[g][2] = fmaf(h, w.z, acc[g][2]);
                acc[g][3] = fmaf(h, w.w, acc[g][3]);
            }
        }
#pragma unroll
        for (int g = 0; g < 4; g++) {
            int node = base + n0 + g;
            if (node < N) {
                size_t idx = (size_t)node * 192 + p * 64 + fb;
                __half2 h01 = __floats2half2_rn(acc[g][0] + b2s[p * 64 + fb + 0],
                                                acc[g][1] + b2s[p * 64 + fb + 1]);
                __half2 h23 = __floats2half2_rn(acc[g][2] + b2s[p * 64 + fb + 2],
                                                acc[g][3] + b2s[p * 64 + fb + 3]);
                reinterpret_cast<__half2*>(&g_so16[idx])[0] = h01;
                reinterpret_cast<__half2*>(&g_so16[idx])[1] = h23;
            }
        }
    }
}

// ---------------------------------------------------------------------------
// Kernel 2: init packed layouts. Thread per (node,c), c in 0..63.
// ---------------------------------------------------------------------------
__global__ void init_pack_kernel(const float* __restrict__ nvec, int total)
{
    int i = blockIdx.x * blockDim.x + threadIdx.x;
    if (i >= total) return;
    int node = i >> 6, c = i & 63;
    size_t nb = (size_t)node * 192;
    float v0 = nvec[nb + c];
    float v1 = nvec[nb + 64 + c];
    float v2 = nvec[nb + 128 + c];
    g_accv[i] = make_float4(v0, v1, v2, 0.f);
    float so_c  = __half2float(g_so16[nb + c]);
    float so64  = __half2float(g_so16[nb + 64 + c]);
    __half2 a = __floats2half2_rn(v0 * so_c, v1 * so_c);
    __half2 b = __floats2half2_rn(v2 * so_c, so64);
    g_pnv[i] = make_uint2(h2_as_u32(a), h2_as_u32(b));
    if (c < 32)
        g_sos[(size_t)node * 32 + c] =
            __halves2half2(g_so16[nb + 128 + 2 * c], g_so16[nb + 129 + 2 * c]);
}

// ---------------------------------------------------------------------------
// Kernel 4: unpermute g_accv -> out_v
// ---------------------------------------------------------------------------
__global__ void unpack_kernel(float* __restrict__ out_v, int total)
{
    int i = blockIdx.x * blockDim.x + threadIdx.x;
    if (i >= total) return;
    int node = i >> 6, c = i & 63;
    float4 a = g_accv[i];
    size_t nb = (size_t)node * 192;
    out_v[nb + c]       = a.x;
    out_v[nb + 64 + c]  = a.y;
    out_v[nb + 128 + c] = a.z;
}

// ---------------------------------------------------------------------------
// Kernel 3: edge kernel. 192 threads, 64 edges/tile, double-buffered smem,
// ONE barrier per tile. Scalar warps (4-5) produce tile t+1 meta+rbf while
// vec warps consume tile t; Chebyshev recurrence for rbf (3 MUFU/edge).
// ---------------------------------------------------------------------------
__global__ void __launch_bounds__(192, 5) edge_kernel(
    const void* __restrict__ edge_raw, const float* __restrict__ ediff,
    const float* __restrict__ edist, const float* __restrict__ Wf,
    const float* __restrict__ bf,
    float* __restrict__ out_s,
    int E, int ntiles)
{
    __shared__ __align__(16) float rbf_s[2][20 * 64];  // [buf][n][e]
    __shared__ __align__(16) float4 meta_s[2][64];     // (u0,u1,u2,cut)
    __shared__ __align__(8)  int2 sd_s[2][64];         // (src,dst)

    int tid  = threadIdx.x;
    int wid  = tid >> 5;
    int lane = tid & 31;
    int is64 = g_edge_is64;
    const int* e32 = (const int*)edge_raw;
    const long long* e64 = (const long long*)edge_raw;

    bool is_vec = (wid < 4);
    int eoff = is_vec ? ((wid & 2) ? 32 : 0) : ((wid == 5) ? 32 : 0);
    int cA, cB;
    if (is_vec) {
        int cc = ((wid & 1) << 5) + lane;  // 0..63
        cA = cc; cB = 64 + cc;
    } else {
        cA = 128 + 2 * lane; cB = cA + 1;  // adjacent pair
    }

    float wfA[20], wfB[20];
#pragma unroll
    for (int n = 0; n < 20; n++) {
        wfA[n] = __ldg(&Wf[n * 192 + cA]);
        wfB[n] = __ldg(&Wf[n * 192 + cB]);
    }
    float bfA = __ldg(&bf[cA]);
    float bfB = __ldg(&bf[cB]);
    int c = cA & 63;  // channel within 64-block (valid for vec warps)
    int me = tid - 128;  // 0..63 for warps 4-5 (meta producers)

    // meta+rbf producer: warps 4-5 fill buf for tile t
    auto fill = [&](int t, int buf) {
        if (me < 0) return;
        int e = t * 64 + me;
        float d = 1.f, u0 = 0.f, u1 = 0.f, u2 = 0.f;
        int sv = 0, dv = 0;
        bool valid = (e < E);
        if (valid) {
            d = __ldg(&edist[e]);
            if (is64) {
                dv = (int)e64[2 * (size_t)e + 0];
                sv = (int)e64[2 * (size_t)e + 1];
            } else {
                dv = e32[2 * (size_t)e + 0];
                sv = e32[2 * (size_t)e + 1];
            }
            u0 = __ldg(&ediff[3 * (size_t)e + 0]);
            u1 = __ldg(&ediff[3 * (size_t)e + 1]);
            u2 = __ldg(&ediff[3 * (size_t)e + 2]);
        }
        float inv = valid ? __frcp_rn(d) : 0.f;
        float x = d * (PI_F / CUTOFF_F);
        float sx, cx;
        __sincosf(x, &sx, &cx);
        float cut = (valid && d < CUTOFF_F) ? 0.5f * (cx + 1.f) : 0.f;
        sd_s[buf][me] = make_int2(sv, dv);
        meta_s[buf][me] = make_float4(u0 * inv, u1 * inv, u2 * inv, cut);
        float two_c = 2.f * cx;
        float s_prev = 0.f, s_cur = sx;
        if (!valid) { s_cur = 0.f; two_c = 0.f; }
#pragma unroll
        for (int n = 0; n < 20; n++) {
            rbf_s[buf][n * 64 + me] = s_cur * inv;
            float s_next = fmaf(two_c, s_cur, -s_prev);
            s_prev = s_cur;
            s_cur = s_next;
        }
    };

    // prologue: fill buf 0 for the first tile
    fill(blockIdx.x, 0);
    int phase = 0;

    for (int t = blockIdx.x; t < ntiles; t += gridDim.x) {
        __syncthreads();  // buf[phase] ready; buf[phase^1] free (readers done)

        // producers: fill next tile into the other buffer
        int nt = t + gridDim.x;
        if (nt < ntiles) fill(nt, phase ^ 1);

        // consumers: matvec + epilogue on buf[phase]
        const float* rbf_p = rbf_s[phase];
        const float4* meta_p = meta_s[phase];
        const int2* sd_p = sd_s[phase];

#pragma unroll 1
        for (int g = 0; g < 8; g++) {
            unsigned long long a01 = 0ull, a23 = 0ull;
            unsigned long long b01 = 0ull, b23 = 0ull;
#pragma unroll
            for (int n = 0; n < 20; n++) {
                ulonglong2 rr = *reinterpret_cast<const ulonglong2*>(
                    &rbf_p[n * 64 + eoff + g * 4]);
                unsigned long long wA = pack2(wfA[n]);
                unsigned long long wB = pack2(wfB[n]);
                a01 = fma2(rr.x, wA, a01);
                a23 = fma2(rr.y, wA, a23);
                b01 = fma2(rr.x, wB, b01);
                b23 = fma2(rr.y, wB, b23);
            }
            float fa[4], fb[4];
            fa[0] = __uint_as_float((unsigned)a01);
            fa[1] = __uint_as_float((unsigned)(a01 >> 32));
            fa[2] = __uint_as_float((unsigned)a23);
            fa[3] = __uint_as_float((unsigned)(a23 >> 32));
            fb[0] = __uint_as_float((unsigned)b01);
            fb[1] = __uint_as_float((unsigned)(b01 >> 32));
            fb[2] = __uint_as_float((unsigned)b23);
            fb[3] = __uint_as_float((unsigned)(b23 >> 32));

            if (is_vec) {
#pragma unroll
                for (int j = 0; j < 4; j++) {
                    int e = eoff + g * 4 + j;
                    int2 sd = sd_p[e];
                    float4 mu = meta_p[e];
                    uint2 p = __ldg(&g_pnv[(unsigned)sd.x * 64u + c]);
                    float2 p01 = __half22float2(u32_as_h2(p.x));
                    float2 p2s = __half22float2(u32_as_h2(p.y));
                    float A = (fa[j] + bfA) * mu.w;
                    float B = (fb[j] + bfB) * mu.w * p2s.y;
                    float m0 = fmaf(p01.x, A, B * mu.x);
                    float m1 = fmaf(p01.y, A, B * mu.y);
                    float m2 = fmaf(p2s.x, A, B * mu.z);
                    red_v4((float*)&g_accv[(unsigned)sd.y * 64u + c], m0, m1, m2, 0.f);
                }
            } else {
#pragma unroll
                for (int j = 0; j < 4; j++) {
                    int e = eoff + g * 4 + j;
                    int2 sd = sd_p[e];
                    float cut = meta_p[e].w;
                    __half2 ss = __ldg(&g_sos[(unsigned)sd.x * 32u + lane]);
                    float2 ssf = __half22float2(ss);
                    float msA = (fa[j] + bfA) * cut * ssf.x;
                    float msB = (fb[j] + bfB) * cut * ssf.y;
                    red_v2(&out_s[(unsigned)sd.y * 64u + 2 * lane], msA, msB);
                }
            }
        }
        phase ^= 1;
    }
}

// ---------------------------------------------------------------------------
extern "C" void kernel_launch(void* const* d_in, const int* in_sizes, int n_in,
                              void* d_out, int out_size)
{
    const float* ns     = (const float*)d_in[0];
    const float* nvec   = (const float*)d_in[1];
    const void*  ed     = (const void*)d_in[2];
    const float* ediff  = (const float*)d_in[3];
    const float* edist  = (const float*)d_in[4];
    const float* W1     = (const float*)d_in[5];
    const float* b1     = (const float*)d_in[6];
    const float* W2     = (const float*)d_in[7];
    const float* b2     = (const float*)d_in[8];
    const float* Wf     = (const float*)d_in[9];
    const float* bf     = (const float*)d_in[10];

    int N = in_sizes[0] / 64;
    int E = in_sizes[4];  // edge_dist has E elements

    float* out_s = (float*)d_out;
    float* out_v = out_s + (size_t)N * 64;

    // 0) detect edge index dtype (int32 vs int64)
    int n_check = (E < 1024) ? E : 1024;
    detect_kernel<<<1, 256>>>((const int*)ed, n_check);

    // 1) node MLP (+ scalar residual init, linear fp16 scalar_out)
    gemm_kernel<<<(N + 31) / 32, 128>>>(ns, W1, b1, W2, b2, out_s, N);

    // 2) init packed layouts (accv residual, pnv, sos)
    int total = N * 64;
    init_pack_kernel<<<(total + 255) / 256, 256>>>(nvec, total);

    // 3) edge messages + scatter
    int ntiles = (E + 63) / 64;
    int grid = ntiles < 740 ? ntiles : 740;
    edge_kernel<<<grid, 192>>>(ed, ediff, edist, Wf, bf,
                               out_s, E, ntiles);

    // 4) unpermute vector accumulator into out_v
    unpack_kernel<<<(total + 255) / 256, 256>>>(out_v, total);
}